// round 7
// baseline (speedup 1.0000x reference)
#include <cuda_runtime.h>
#include <cstdint>

#define B_   256
#define T_   100
#define NIN  700
#define KP   704            // NIN padded to multiple of 16
#define NN   2068
#define NNP  2176           // NN padded to multiple of 128
#define NOUT 20
#define TAU  0.6f
#define KC   320            // Eigen kc panel size
#define MROWS (B_ * T_)     // 25600

// ---------------- scratch (device globals; no runtime allocation) ----------
__device__ float g_ffp[3][(size_t)MROWS * NNP];  // per-panel ff partials
__device__ float g_xp[(size_t)MROWS * KP];       // x staged: [r = t*B+b][k], zero-padded
__device__ float g_w1t[(size_t)KP * NNP];        // W_fc1^T zero-padded: [k][n]

// ---------------- staging ---------------------------------------------------
__global__ void pad_x_kernel(const float* __restrict__ x) {
    size_t idx = (size_t)blockIdx.x * blockDim.x + threadIdx.x;
    if (idx < (size_t)MROWS * KP) {
        int r = (int)(idx / KP);
        int k = (int)(idx - (size_t)r * KP);
        int t = r >> 8;                 // r = t*256 + b
        int b = r & 255;
        g_xp[idx] = (k < NIN) ? x[((size_t)b * T_ + t) * NIN + k] : 0.0f;
    }
}

__global__ void pad_w1t_kernel(const float* __restrict__ W1) {
    size_t idx = (size_t)blockIdx.x * blockDim.x + threadIdx.x;
    if (idx < (size_t)KP * NNP) {
        int k = (int)(idx / NNP);
        int n = (int)(idx - (size_t)k * NNP);
        g_w1t[idx] = (k < NIN && n < NN) ? W1[(size_t)n * NIN + k] : 0.0f;
    }
}

// ---------------- packed dual-fp32 FMA (SASS FFMA2; bitwise IEEE per lane) --
__device__ __forceinline__ void fma2(uint64_t& d, uint64_t a, uint64_t b) {
    asm("fma.rn.f32x2 %0, %1, %2, %0;" : "+l"(d) : "l"(a), "l"(b));
}
__device__ __forceinline__ uint64_t bcast2(float a) {
    uint64_t r;
    asm("mov.b64 %0, {%1, %1};" : "=l"(r) : "f"(a));
    return r;
}

// ---------------- phase 1: per-panel GEMM slabs (double-buffered, FFMA2) ----
// Slab z: K range [z*320, z*320+KL), KL = 320,320,64(zero-padded 640..704).
// Per output element: single sequential-k FMA chain == Eigen in-panel order.
#define BM 128
#define BN 128
#define BK 16

__global__ __launch_bounds__(256, 2) void gemm_slab_kernel() {
    __shared__ float As[2][BK][BM];
    __shared__ float Bs[2][BK][BN];

    int tid  = threadIdx.x;
    int z    = blockIdx.z;
    int row0 = blockIdx.y * BM;
    int col0 = blockIdx.x * BN;
    int k0g  = z * KC;
    int KL   = (z == 2) ? (KP - 2 * KC) : KC;
    int nT   = KL / BK;

    float* C = g_ffp[0] + (size_t)z * MROWS * NNP;

    int arow = tid >> 1;
    int asub = (tid & 1) * 8;
    const float* ap = g_xp + (size_t)(row0 + arow) * KP + k0g + asub;

    int bn   = tid & 127;
    int bsub = (tid >> 7) * 8;
    const float* bp = g_w1t + (size_t)(k0g + bsub) * NNP + (col0 + bn);

    int tr = (tid >> 4) * 8;
    int tc = (tid & 15) * 8;

    float4 ra0, ra1;
    float  rbv[8];

    // prolog: load tile 0 into regs, stage into buffer 0
    ra0 = *(const float4*)(ap);
    ra1 = *(const float4*)(ap + 4);
    #pragma unroll
    for (int i = 0; i < 8; i++) rbv[i] = bp[(size_t)i * NNP];

    As[0][asub + 0][arow] = ra0.x; As[0][asub + 1][arow] = ra0.y;
    As[0][asub + 2][arow] = ra0.z; As[0][asub + 3][arow] = ra0.w;
    As[0][asub + 4][arow] = ra1.x; As[0][asub + 5][arow] = ra1.y;
    As[0][asub + 6][arow] = ra1.z; As[0][asub + 7][arow] = ra1.w;
    #pragma unroll
    for (int i = 0; i < 8; i++) Bs[0][bsub + i][bn] = rbv[i];
    __syncthreads();

    // packed accumulators: acc64[i][jj] = (C[i][2jj], C[i][2jj+1])
    uint64_t acc64[8][4];
    #pragma unroll
    for (int i = 0; i < 8; i++)
        #pragma unroll
        for (int jj = 0; jj < 4; jj++) acc64[i][jj] = 0ull;

    for (int tI = 0; tI < nT; tI++) {
        int  buf  = tI & 1;
        bool more = (tI + 1 < nT);

        if (more) {                               // prefetch next tile to regs
            const float* apn = ap + (tI + 1) * BK;
            ra0 = *(const float4*)(apn);
            ra1 = *(const float4*)(apn + 4);
            const float* bpn = bp + (size_t)(tI + 1) * BK * NNP;
            #pragma unroll
            for (int i = 0; i < 8; i++) rbv[i] = bpn[(size_t)i * NNP];
        }

        #pragma unroll
        for (int kk = 0; kk < BK; kk++) {
            float a[8];
            *(float4*)&a[0] = *(const float4*)&As[buf][kk][tr];
            *(float4*)&a[4] = *(const float4*)&As[buf][kk][tr + 4];

            // B pairs load directly as packed f32x2 operands (16B aligned: tc % 8 == 0)
            ulonglong2 b01 = *(const ulonglong2*)&Bs[buf][kk][tc];
            ulonglong2 b23 = *(const ulonglong2*)&Bs[buf][kk][tc + 4];
            uint64_t bv[4] = { b01.x, b01.y, b23.x, b23.y };

            uint64_t aa[8];
            #pragma unroll
            for (int i = 0; i < 8; i++) aa[i] = bcast2(a[i]);

            #pragma unroll
            for (int i = 0; i < 8; i++)
                #pragma unroll
                for (int jj = 0; jj < 4; jj++)
                    fma2(acc64[i][jj], aa[i], bv[jj]);
        }

        if (more) {                               // stage next tile
            int nb = buf ^ 1;
            As[nb][asub + 0][arow] = ra0.x; As[nb][asub + 1][arow] = ra0.y;
            As[nb][asub + 2][arow] = ra0.z; As[nb][asub + 3][arow] = ra0.w;
            As[nb][asub + 4][arow] = ra1.x; As[nb][asub + 5][arow] = ra1.y;
            As[nb][asub + 6][arow] = ra1.z; As[nb][asub + 7][arow] = ra1.w;
            #pragma unroll
            for (int i = 0; i < 8; i++) Bs[nb][bsub + i][bn] = rbv[i];
        }
        __syncthreads();
    }

    #pragma unroll
    for (int i = 0; i < 8; i++) {
        float* crow = C + (size_t)(row0 + tr + i) * NNP + (col0 + tc);
        *(float4*)(crow)     = *(float4*)&acc64[i][0];   // (lo,hi) pairs are in n-order
        *(float4*)(crow + 4) = *(float4*)&acc64[i][2];
    }
}

// ---------------- phase 2: fused 100-step LIF, one CTA per batch -------------
// 512 threads; thread covers n = j*512+tid, j=0..3 full, j=4 only tid<20.
// Per step (bitwise == reference):
//   ff  = fadd(fadd(p0,p1),p2)
//   rec = kc=320-panel fold of ascending active-row adds (unroll-4 gather)
//   cur = fadd(ff,rec); mem = fadd(fmul(fmul(TAU,mem),fsub(1,spk)),cur); spk = mem>=1
#define NT   512
#define SCPT 5
#define NWP  16

__device__ __forceinline__ void flush_panel(float* rec, float* part) {
    #pragma unroll
    for (int j = 0; j < SCPT; j++) {
        rec[j]  = __fadd_rn(rec[j], part[j]);
        part[j] = 0.0f;
    }
}
__device__ __forceinline__ void add_row(float* part, const float* v) {
    #pragma unroll
    for (int j = 0; j < SCPT; j++) part[j] = __fadd_rn(part[j], v[j]);
}

__global__ __launch_bounds__(NT, 2) void steps_kernel(const float* __restrict__ Wrec,
                                                      float* __restrict__ out) {
    __shared__ int s_list[NN];
    __shared__ int s_wcnt[SCPT][NWP];

    int b    = blockIdx.x;
    int tid  = threadIdx.x;
    int wid  = tid >> 5;
    int lane = tid & 31;
    unsigned ltmask = (1u << lane) - 1u;
    bool tv  = (tid < NOUT);

    float m[SCPT], s[SCPT];
    #pragma unroll
    for (int j = 0; j < SCPT; j++) { m[j] = 0.0f; s[j] = 0.0f; }

    const float* ff0 = g_ffp[0];
    const float* ff1 = g_ffp[1];
    const float* ff2 = g_ffp[2];

    for (int t = 0; t < T_; t++) {
        // ---- ff partial fold (independent loads, issued first) ----
        size_t rbase = ((size_t)t * B_ + b) * NNP;
        float ffv[SCPT];
        #pragma unroll
        for (int j = 0; j < SCPT; j++) {
            int n = j * NT + tid;
            bool v = (j < 4) || tv;
            ffv[j] = v ? __fadd_rn(__fadd_rn(ff0[rbase + n], ff1[rbase + n]), ff2[rbase + n])
                       : 0.0f;
        }

        // ---- build ascending active list (ballot + cross-warp prefix) ----
        unsigned msk[SCPT];
        #pragma unroll
        for (int j = 0; j < SCPT; j++) {
            bool a = ((j < 4) || tv) && (s[j] != 0.0f);
            msk[j] = __ballot_sync(0xffffffffu, a);
            if (lane == 0) s_wcnt[j][wid] = __popc(msk[j]);
        }
        __syncthreads();

        int base[SCPT];
        int cnt;
        {
            int rb = 0;
            #pragma unroll
            for (int jj = 0; jj < SCPT; jj++) {
                int off = 0, rowtot = 0;
                #pragma unroll
                for (int w = 0; w < NWP; w++) {
                    int c = s_wcnt[jj][w];
                    if (w < wid) off += c;
                    rowtot += c;
                }
                base[jj] = rb + off;
                rb += rowtot;
            }
            cnt = rb;
        }

        #pragma unroll
        for (int j = 0; j < SCPT; j++) {
            bool a = ((j < 4) || tv) && (s[j] != 0.0f);
            if (a) s_list[base[j] + __popc(msk[j] & ltmask)] = j * NT + tid;
        }
        __syncthreads();

        // ---- rec: panel-folded ascending adds, unroll-4 batched loads ----
        float rec[SCPT], part[SCPT];
        #pragma unroll
        for (int j = 0; j < SCPT; j++) { rec[j] = 0.0f; part[j] = 0.0f; }

        int curp = 0;
        int i = 0;
        for (; i + 4 <= cnt; i += 4) {
            int m0 = s_list[i + 0], m1 = s_list[i + 1];
            int m2 = s_list[i + 2], m3 = s_list[i + 3];
            const float* w0 = Wrec + (size_t)m0 * NN;
            const float* w1 = Wrec + (size_t)m1 * NN;
            const float* w2 = Wrec + (size_t)m2 * NN;
            const float* w3 = Wrec + (size_t)m3 * NN;
            float v0[SCPT], v1[SCPT], v2[SCPT], v3[SCPT];
            #pragma unroll
            for (int j = 0; j < SCPT; j++) {
                int n = j * NT + tid;
                bool v = (j < 4) || tv;
                v0[j] = v ? w0[n] : 0.0f;
                v1[j] = v ? w1[n] : 0.0f;
                v2[j] = v ? w2[n] : 0.0f;
                v3[j] = v ? w3[n] : 0.0f;
            }
            int p;
            p = m0 / KC; if (p != curp) { flush_panel(rec, part); curp = p; } add_row(part, v0);
            p = m1 / KC; if (p != curp) { flush_panel(rec, part); curp = p; } add_row(part, v1);
            p = m2 / KC; if (p != curp) { flush_panel(rec, part); curp = p; } add_row(part, v2);
            p = m3 / KC; if (p != curp) { flush_panel(rec, part); curp = p; } add_row(part, v3);
        }
        for (; i < cnt; i++) {
            int mr = s_list[i];
            const float* wr = Wrec + (size_t)mr * NN;
            float v0[SCPT];
            #pragma unroll
            for (int j = 0; j < SCPT; j++) {
                int n = j * NT + tid;
                v0[j] = ((j < 4) || tv) ? wr[n] : 0.0f;
            }
            int p = mr / KC;
            if (p != curp) { flush_panel(rec, part); curp = p; }
            add_row(part, v0);
        }
        flush_panel(rec, part);   // final panel fold into rec

        // ---- membrane update + spikes ----
        #pragma unroll
        for (int j = 0; j < SCPT; j++) {
            if ((j < 4) || tv) {
                float cur = __fadd_rn(ffv[j], rec[j]);
                float t1  = __fmul_rn(TAU, m[j]);
                float t2  = __fsub_rn(1.0f, s[j]);
                float t3  = __fmul_rn(t1, t2);
                float mn  = __fadd_rn(t3, cur);
                m[j] = mn;
                s[j] = (mn >= 1.0f) ? 1.0f : 0.0f;
            }
        }
        if (tv)
            out[((size_t)b * T_ + t) * NOUT + tid] = s[4];

        __syncthreads();   // protect s_list/s_wcnt reuse next step
    }
}

// ---------------- launch -----------------------------------------------------
extern "C" void kernel_launch(void* const* d_in, const int* in_sizes, int n_in,
                              void* d_out, int out_size) {
    const float* x  = (const float*)d_in[0];   // [B, T, NIN]
    const float* W1 = (const float*)d_in[1];   // [NN, NIN]
    const float* Wr = (const float*)d_in[2];   // [NN, NN]
    float* out = (float*)d_out;                // [B, T, NOUT]

    {
        size_t n = (size_t)MROWS * KP;
        pad_x_kernel<<<(unsigned)((n + 255) / 256), 256>>>(x);
    }
    {
        size_t n = (size_t)KP * NNP;
        pad_w1t_kernel<<<(unsigned)((n + 255) / 256), 256>>>(W1);
    }

    dim3 ggrid(NNP / BN, MROWS / BM, 3);   // 17 x 200 x 3 slabs
    gemm_slab_kernel<<<ggrid, 256>>>();

    steps_kernel<<<B_, NT>>>(Wr, out);
}